// round 12
// baseline (speedup 1.0000x reference)
#include <cuda_runtime.h>
#include <math.h>

#define BATCH 8
#define HW 1024
#define HS 512
#define NPIX (HS*HS)
#define NPTS 10
#define KP 512
#define SORTN 8192
#define ER 22
#define EC 38

// dynamic smem layout for k3 (bytes):
//   [0, 58752)        u64 sIn2[12*18*34]    activations pre-packed {v,v}
//   [58752, 65440)    float sE[2*ER*EC]
//   [65440, 71424)    float sH[2*ER*34]
//   [71424, 71812)    float sSc[32], sSh[32], sW2[32], sB2
#define K3_SMEM 71936

// ---------------- scratch (device globals; no allocation) ----------------
__device__ float g_sal[BATCH*NPIX];
__device__ float g_cand_val[BATCH*NPIX];
__device__ int   g_cand_idx[BATCH*NPIX];
__device__ int   g_cand_cnt[BATCH];
__device__ int   g_rowflag[BATCH*HW];
__device__ int   g_colflag[BATCH*HW];

// reordered conv1 weights: [(c*9+tap)*8 + q] = ulonglong2{oc 4q..4q+1, oc 4q+2..4q+3}
__device__ __align__(16) float g_wre[3456];
__constant__ __align__(16) ulonglong2 cW[864];

// ---------------- packed f32x2 helpers ----------------
__device__ __forceinline__ unsigned long long fma2(unsigned long long a,
                                                   unsigned long long b,
                                                   unsigned long long c){
    unsigned long long d;
    asm("fma.rn.f32x2 %0, %1, %2, %3;" : "=l"(d) : "l"(a), "l"(b), "l"(c));
    return d;
}
__device__ __forceinline__ unsigned long long pack2(float v){
    unsigned long long d;
    asm("mov.b64 %0, {%1, %1};" : "=l"(d) : "f"(v));
    return d;
}
__device__ __forceinline__ void unpack2(unsigned long long p, float& lo, float& hi){
    asm("mov.b64 {%0, %1}, %2;" : "=f"(lo), "=f"(hi) : "l"(p));
}

// ---------------- KW: reorder conv1 weights + zero flags/counters ----------------
__global__ void kw_reorder(const float* __restrict__ w1){
    int l = blockIdx.x*256 + threadIdx.x;
    if (l < 3456){
        int tl = l >> 5, oc = l & 31;
        g_wre[tl*32 + oc] = w1[oc*108 + tl];
    }
    if (l < BATCH*HW){ g_rowflag[l] = 0; g_colflag[l] = 0; }
    if (l < BATCH) g_cand_cnt[l] = 0;
}

// ---------------- K3: fused DWT+energy+smooth+conv+BN+GELU+conv1x1+sigmoid ----------------
__global__ __launch_bounds__(256, 2) void k3_conv(
    const float* __restrict__ rgb, const float* __restrict__ dep,
    const float* __restrict__ b1,
    const float* __restrict__ gam, const float* __restrict__ bet,
    const float* __restrict__ mu,  const float* __restrict__ var,
    const float* __restrict__ w2,  const float* __restrict__ b2)
{
    extern __shared__ unsigned char sm[];
    unsigned long long* sIn2 = (unsigned long long*)sm;          // [12*612] packed {v,v}
    float* sE  = (float*)(sm + 58752);
    float* sH  = (float*)(sm + 65440);
    float* sSc = (float*)(sm + 71424);
    float* sSh = sSc + 32;
    float* sW2 = sSh + 32;
    float* sB2 = sW2 + 32;
    int tid = threadIdx.x;
    int b = blockIdx.z;
    int ty0 = blockIdx.y*16, tx0 = blockIdx.x*32;

    // normalized separable gaussian (identical to former k2)
    const float e0 = 1.0f, e1 = 0.60653065971f, e2 = 0.13533528323f;
    const float sum1 = e0 + 2.f*e1 + 2.f*e2;
    const float w0 = e0/sum1, w1c = e1/sum1, w2c = e2/sum1;

    size_t plane = (size_t)HW*HW;
    const float* RP = rgb + (size_t)b*3*plane;
    const float* GP = RP + plane;
    const float* BP = GP + plane;
    const float* DP = dep + (size_t)b*plane;

    // ---- phase A: gray + Haar DWT + energy on the 22x38 halo region ----
    for (int l = tid; l < ER*EC; l += 256){
        int ey = l / EC, ex = l - ey*EC;
        int gy = ty0 - 3 + ey, gx = tx0 - 3 + ex;
        bool in = (gy >= 0 && gy < HS && gx >= 0 && gx < HS);
        float er = 0.f, ed = 0.f;
        float LLr=0.f,LHr=0.f,HLr=0.f,HHr=0.f, LLd=0.f,LHd=0.f,HLd=0.f,HHd=0.f;
        if (in){
            int i00 = (2*gy)*HW + 2*gx;
            int i01 = i00 + 1, i10 = i00 + HW, i11 = i00 + HW + 1;
            float v00 = (RP[i00]+GP[i00]+BP[i00])/3.0f;
            float v01 = (RP[i01]+GP[i01]+BP[i01])/3.0f;
            float v10 = (RP[i10]+GP[i10]+BP[i10])/3.0f;
            float v11 = (RP[i11]+GP[i11]+BP[i11])/3.0f;
            {
                float a=v00*0.5f, c2=v10*0.5f, e22=v01*0.5f, f2=v11*0.5f;
                LLr=a+c2; LHr=a-c2; HLr=e22+f2; HHr=e22-f2;
                er = sqrtf(LHr*LHr+HLr*HLr+HHr*HHr+1e-8f);
            }
            {
                float a=DP[i00]*0.5f, c2=DP[i10]*0.5f, e22=DP[i01]*0.5f, f2=DP[i11]*0.5f;
                LLd=a+c2; LHd=a-c2; HLd=e22+f2; HHd=e22-f2;
                ed = sqrtf(LHd*LHd+HLd*HLd+HHd*HHd+1e-8f);
            }
        }
        sE[l] = er; sE[ER*EC + l] = ed;
        int iy = ey - 2, ix = ex - 2;
        if (iy >= 0 && iy < 18 && ix >= 0 && ix < 34){
            int o = iy*34 + ix;
            sIn2[0*612+o]=pack2(LLr); sIn2[1*612+o]=pack2(LHr);
            sIn2[2*612+o]=pack2(HLr); sIn2[3*612+o]=pack2(HHr);
            sIn2[4*612+o]=pack2(LLd); sIn2[5*612+o]=pack2(LHd);
            sIn2[6*612+o]=pack2(HLd); sIn2[7*612+o]=pack2(HHd);
            sIn2[8*612+o]=pack2(er);  sIn2[9*612+o]=pack2(ed);
        }
    }
    if (tid < 32){
        float inv = 1.0f/sqrtf(var[tid] + 1e-5f);
        float sc = gam[tid]*inv;
        sSc[tid] = sc;
        sSh[tid] = (b1[tid] - mu[tid])*sc + bet[tid];
        sW2[tid] = w2[tid];
    }
    if (tid == 0) sB2[0] = b2[0];
    __syncthreads();

    // ---- phase B: horizontal smooth (identical formula to former k2) ----
    for (int l = tid; l < 2*ER*34; l += 256){
        int ch = l / (ER*34);
        int rr = l - ch*(ER*34);
        int r = rr/34, c = rr - r*34;
        const float* e = sE + ch*ER*EC + r*EC + c;
        sH[l] = w2c*(e[0]+e[4]) + w1c*(e[1]+e[3]) + w0*e[2];
    }
    __syncthreads();

    // ---- phase C: vertical smooth -> channels 10, 11 (ZERO outside image: conv pad) ----
    for (int l = tid; l < 2*612; l += 256){
        int ch = l / 612;
        int o = l - ch*612;
        int iy = o/34, ix = o - iy*34;
        int gy = ty0 + iy - 1, gx = tx0 + ix - 1;          // image coords of this sIn cell
        float v = 0.f;
        if (gy >= 0 && gy < HS && gx >= 0 && gx < HS){     // conv1 zero-padding
            const float* h = sH + ch*(ER*34) + iy*34 + ix;
            v = w2c*(h[0]+h[4*34]) + w1c*(h[1*34]+h[3*34]) + w0*h[2*34];
        }
        sIn2[(10+ch)*612 + o] = pack2(v);
    }
    __syncthreads();

    // ---- mainloop: conv3x3(12->32), f32x2, pre-packed activations, weights in constant ----
    int ty = tid >> 5, tx = tid & 31;
    unsigned long long accA[16], accB[16];
    #pragma unroll
    for (int i=0;i<16;i++){ accA[i] = 0ULL; accB[i] = 0ULL; }
    for (int c=0; c<12; c++){
        #pragma unroll
        for (int tap=0; tap<9; tap++){
            int ky = tap/3, kx = tap%3;
            unsigned long long v0 = sIn2[c*612 + (ty+ky)*34 + (tx+kx)];
            unsigned long long v1 = sIn2[c*612 + (ty+8+ky)*34 + (tx+kx)];
            const ulonglong2* wrow = cW + (c*9+tap)*8;
            #pragma unroll
            for (int q=0;q<8;q++){
                ulonglong2 wp = wrow[q];
                accA[2*q+0] = fma2(v0, wp.x, accA[2*q+0]);
                accA[2*q+1] = fma2(v0, wp.y, accA[2*q+1]);
                accB[2*q+0] = fma2(v1, wp.x, accB[2*q+0]);
                accB[2*q+1] = fma2(v1, wp.y, accB[2*q+1]);
            }
        }
    }
    float zA = sB2[0], zB = sB2[0];
    #pragma unroll
    for (int j=0; j<16; j++){
        float a0, a1, b0, b1v;
        unpack2(accA[j], a0, a1);
        unpack2(accB[j], b0, b1v);
        int oc = 2*j;
        {
            float xv = fmaf(a0, sSc[oc], sSh[oc]);
            float gl = 0.5f*xv*(1.0f + tanhf(0.7978845608f*(xv + 0.044715f*xv*xv*xv)));
            zA = fmaf(gl, sW2[oc], zA);
        }
        {
            float xv = fmaf(a1, sSc[oc+1], sSh[oc+1]);
            float gl = 0.5f*xv*(1.0f + tanhf(0.7978845608f*(xv + 0.044715f*xv*xv*xv)));
            zA = fmaf(gl, sW2[oc+1], zA);
        }
        {
            float xv = fmaf(b0, sSc[oc], sSh[oc]);
            float gl = 0.5f*xv*(1.0f + tanhf(0.7978845608f*(xv + 0.044715f*xv*xv*xv)));
            zB = fmaf(gl, sW2[oc], zB);
        }
        {
            float xv = fmaf(b1v, sSc[oc+1], sSh[oc+1]);
            float gl = 0.5f*xv*(1.0f + tanhf(0.7978845608f*(xv + 0.044715f*xv*xv*xv)));
            zB = fmaf(gl, sW2[oc+1], zB);
        }
    }
    float* S = g_sal + (size_t)b*NPIX;
    S[(ty0+ty)*HS + (tx0+tx)]     = 1.0f/(1.0f + expf(-zA));
    S[(ty0+ty+8)*HS + (tx0+tx)]   = 1.0f/(1.0f + expf(-zB));
}

// ---------------- K45: fused bilinear x2 upsample + flags + peaks ----------------
__global__ void k45_mask_peaks(float* __restrict__ masks){
    __shared__ int colAny[64];
    __shared__ int rowAny[16];
    __shared__ float sv[256];
    __shared__ int   si[256];
    __shared__ int   scnt, sbase;
    int tx = threadIdx.x, ty = threadIdx.y;
    int tid = ty*32 + tx;
    if (tid < 64) colAny[tid] = 0;
    if (tid < 16) rowAny[tid] = 0;
    if (tid == 0) scnt = 0;
    __syncthreads();
    int x = blockIdx.x*32 + tx;
    int y = blockIdx.y*8  + ty;
    int b = blockIdx.z;
    const float* s = g_sal + (size_t)b*NPIX;
    int xm = max(x-1,0), xp = min(x+1,HS-1);
    int ym = max(y-1,0), yp = min(y+1,HS-1);
    float n00=s[ym*HS+xm], n01=s[ym*HS+x], n02=s[ym*HS+xp];
    float n10=s[y*HS+xm],  v  =s[y*HS+x],  n12=s[y*HS+xp];
    float n20=s[yp*HS+xm], n21=s[yp*HS+x], n22=s[yp*HS+xp];
    float mp = fmaxf(fmaxf(fmaxf(n00,n01),fmaxf(n02,n10)),
                     fmaxf(fmaxf(v,n12),fmaxf(fmaxf(n20,n21),n22)));
    bool pk = (v == mp) && (v > 0.f);
    if (pk){
        int p = atomicAdd(&scnt, 1);
        sv[p] = v; si[p] = y*HS + x;
    }
    float m00 = 0.25f*(0.25f*n00 + 0.75f*n01) + 0.75f*(0.25f*n10 + 0.75f*v);
    float m01 = 0.25f*(0.75f*n01 + 0.25f*n02) + 0.75f*(0.75f*v + 0.25f*n12);
    float m10 = 0.75f*(0.25f*n10 + 0.75f*v)   + 0.25f*(0.25f*n20 + 0.75f*n21);
    float m11 = 0.75f*(0.75f*v + 0.25f*n12)   + 0.25f*(0.75f*n21 + 0.25f*n22);
    float* M = masks + (size_t)b*HW*HW;
    *(float2*)&M[(size_t)(2*y)*HW   + 2*x] = make_float2(m00, m01);
    *(float2*)&M[(size_t)(2*y+1)*HW + 2*x] = make_float2(m10, m11);
    bool r0 = (m00 > 0.5f) || (m01 > 0.5f);
    bool r1 = (m10 > 0.5f) || (m11 > 0.5f);
    bool c0 = (m00 > 0.5f) || (m10 > 0.5f);
    bool c1 = (m01 > 0.5f) || (m11 > 0.5f);
    if (r0) rowAny[2*ty] = 1;
    if (r1) rowAny[2*ty+1] = 1;
    if (c0) colAny[2*tx] = 1;
    if (c1) colAny[2*tx+1] = 1;
    __syncthreads();
    if (tid < 16 && rowAny[tid]) atomicOr(&g_rowflag[b*HW + blockIdx.y*16 + tid], 1);
    if (tid < 64 && colAny[tid]) atomicOr(&g_colflag[b*HW + blockIdx.x*64 + tid], 1);
    if (tid == 0 && scnt) sbase = atomicAdd(&g_cand_cnt[b], scnt);
    __syncthreads();
    if (tid < scnt){
        g_cand_val[(size_t)b*NPIX + sbase + tid] = sv[tid];
        g_cand_idx[(size_t)b*NPIX + sbase + tid] = si[tid];
    }
}

// ---------------- K6: points (blocks 0..7) + boxes (blocks 8..15) ----------------
__global__ __launch_bounds__(1024) void k6_points(float* __restrict__ out){
    extern __shared__ unsigned char sraw[];
    int tid = threadIdx.x;

    if (blockIdx.x >= BATCH){
        int b = blockIdx.x - BATCH;
        int* sred = (int*)sraw;
        int rf = g_rowflag[b*HW + tid];
        int cf = g_colflag[b*HW + tid];
        int res[4];
        int init[4] = { rf ? tid : HW, rf ? tid : -1, cf ? tid : HW, cf ? tid : -1 };
        #pragma unroll
        for (int w = 0; w < 4; w++){
            sred[tid] = init[w];
            __syncthreads();
            for (int st = 512; st > 0; st >>= 1){
                if (tid < st){
                    int o = sred[tid+st];
                    sred[tid] = (w == 0 || w == 2) ? min(sred[tid], o) : max(sred[tid], o);
                }
                __syncthreads();
            }
            res[w] = sred[0];
            __syncthreads();
        }
        if (tid == 0){
            float* bx = out + BATCH*NPTS*2 + BATCH*NPTS + b*4;
            if (res[1] >= 0){ bx[0]=(float)res[2]; bx[1]=(float)res[0]; bx[2]=(float)res[3]; bx[3]=(float)res[1]; }
            else            { bx[0]=0.f; bx[1]=0.f; bx[2]=(float)(HW-1); bx[3]=(float)(HW-1); }
        }
        return;
    }

    unsigned long long* keys = (unsigned long long*)sraw;
    unsigned int* hist = (unsigned int*)(sraw + 65536);
    unsigned long long* bestkey = (unsigned long long*)(sraw + 65536);
    int* part = (int*)(sraw + 81920);
    unsigned char* avail = (unsigned char*)(sraw + 86016);
    __shared__ int s_ti[KP];
    __shared__ int sT, sTf, sM, sChi, sCnt, sPick, sCur;
    __shared__ int chosenIdx[NPTS];
    __shared__ int fbIdx[NPTS];
    __shared__ unsigned long long sWin;

    int b = blockIdx.x;
    int N = g_cand_cnt[b];
    if (N > NPIX) N = NPIX;
    int need = min(KP, N);
    const float* cv = g_cand_val + (size_t)b*NPIX;
    const int*   ci = g_cand_idx + (size_t)b*NPIX;

    hist[tid] = 0u; hist[tid+1024] = 0u; hist[tid+2048] = 0u; hist[tid+3072] = 0u;
    if (tid == 0){ sT = 0; sM = 0; sChi = 0; sTf = 0; }
    __syncthreads();
    for (int i = tid; i < N; i += 1024){
        int bin = max(0, min(4095, (int)(cv[i]*4096.0f)));
        atomicAdd(&hist[bin], 1u);
    }
    __syncthreads();
    int t4 = tid*4;
    {
        int h0 = hist[t4], h1 = hist[t4+1], h2 = hist[t4+2], h3 = hist[t4+3];
        part[tid] = h0+h1+h2+h3;
        __syncthreads();
        for (int d = 1; d < 1024; d <<= 1){
            int v = (tid + d < 1024) ? part[tid + d] : 0;
            __syncthreads();
            part[tid] += v;
            __syncthreads();
        }
        int base = part[tid];
        int s1 = base - h0, s2 = s1 - h1, s3 = s2 - h2;
        int bestT = -1;
        if (s3 >= need) bestT = t4+3;
        else if (s2 >= need) bestT = t4+2;
        else if (s1 >= need) bestT = t4+1;
        else if (base >= need) bestT = t4;
        if (bestT >= 0) atomicMax(&sT, bestT);
    }
    __syncthreads();
    int T = sT;
    hist[tid] = 0u; hist[tid+1024] = 0u; hist[tid+2048] = 0u; hist[tid+3072] = 0u;
    __syncthreads();
    for (int i = tid; i < N; i += 1024){
        float v = cv[i];
        int bin = max(0, min(4095, (int)(v*4096.0f)));
        if (bin > T) atomicAdd(&sChi, 1);
        else if (bin == T){
            float frac = v*4096.0f - (float)T;
            int fb = max(0, min(4095, (int)(frac*4096.0f)));
            atomicAdd(&hist[fb], 1u);
        }
    }
    __syncthreads();
    int needF = need - sChi;
    {
        int h0 = hist[t4], h1 = hist[t4+1], h2 = hist[t4+2], h3 = hist[t4+3];
        part[tid] = h0+h1+h2+h3;
        __syncthreads();
        for (int d = 1; d < 1024; d <<= 1){
            int v = (tid + d < 1024) ? part[tid + d] : 0;
            __syncthreads();
            part[tid] += v;
            __syncthreads();
        }
        int base = part[tid];
        int s1 = base - h0, s2 = s1 - h1, s3 = s2 - h2;
        int bestT = -1;
        if (s3 >= needF) bestT = t4+3;
        else if (s2 >= needF) bestT = t4+2;
        else if (s1 >= needF) bestT = t4+1;
        else if (base >= needF) bestT = t4;
        if (bestT >= 0) atomicMax(&sTf, bestT);
    }
    __syncthreads();
    int Tf = sTf;
    for (int i = tid; i < N; i += 1024){
        float v = cv[i];
        int bin = max(0, min(4095, (int)(v*4096.0f)));
        bool take = (bin > T);
        if (!take && bin == T){
            float frac = v*4096.0f - (float)T;
            int fb = max(0, min(4095, (int)(frac*4096.0f)));
            take = (fb >= Tf);
        }
        if (take){
            int p = atomicAdd(&sM, 1);
            if (p < SORTN)
                keys[p] = ((unsigned long long)__float_as_uint(v) << 32)
                        | (unsigned int)(~(unsigned)ci[i]);
        }
    }
    __syncthreads();
    int M = min(sM, SORTN);
    int S = 512;
    while (S < M) S <<= 1;
    for (int i = M + tid; i < S; i += 1024) keys[i] = 0ULL;
    __syncthreads();
    for (int k = 2; k <= S; k <<= 1){
        for (int j = k >> 1; j > 0; j >>= 1){
            for (int i = tid; i < S; i += 1024){
                int ixj = i ^ j;
                if (ixj > i){
                    unsigned long long a = keys[i], c = keys[ixj];
                    bool up = ((i & k) == 0);
                    if ((a > c) == up){ keys[i] = c; keys[ixj] = a; }
                }
            }
            __syncthreads();
        }
    }
    if (tid < KP){
        s_ti[tid] = (int)(~(unsigned)(keys[S-1-tid] & 0xffffffffu));
        avail[tid] = 1;
    }
    __syncthreads();

    int Kv = min(N, KP);
    if (tid == 0){ sCnt = 0; sCur = 0; }
    __syncthreads();
    for (int round = 0; round < NPTS; round++){
        if (tid == 0){
            int i = sCur;
            while (i < Kv && !avail[i]) i++;
            if (i < Kv){
                chosenIdx[sCnt] = s_ti[i];
                sCnt++;
                sPick = i;
                sCur = i + 1;
            } else sPick = -1;
        }
        __syncthreads();
        int i = sPick;
        if (i < 0) break;
        int idx = s_ti[i];
        int xi = idx & (HS-1), yi = idx >> 9;
        if (tid < KP && tid > i && tid < Kv && avail[tid]){
            int dx = (s_ti[tid] & (HS-1)) - xi;
            int dy = (s_ti[tid] >> 9) - yi;
            if (dx*dx + dy*dy < 625) avail[tid] = 0;
        }
        __syncthreads();
    }
    int cnt = sCnt;

    if (cnt < NPTS){
        const float* s = g_sal + (size_t)b*NPIX;
        float lv[NPTS]; int li[NPTS];
        #pragma unroll
        for (int k=0;k<NPTS;k++){ lv[k] = -1e30f; li[k] = 0x7fffffff; }
        for (int p = tid; p < NPIX; p += 1024){
            float v = s[p];
            if (v <= lv[NPTS-1]) continue;
            int y = p >> 9, x = p & (HS-1);
            float mp = v;
            #pragma unroll
            for (int dy=-1; dy<=1; dy++){
                int yy = y + dy; if (yy < 0 || yy >= HS) continue;
                #pragma unroll
                for (int dx=-1; dx<=1; dx++){
                    int xx = x + dx; if (xx < 0 || xx >= HS) continue;
                    mp = fmaxf(mp, s[yy*HS + xx]);
                }
            }
            if (v == mp) continue;
            float cvv = v; int cix = p;
            #pragma unroll
            for (int k=0;k<NPTS;k++){
                bool better = (cvv > lv[k]) || (cvv == lv[k] && cix < li[k]);
                float tv = lv[k]; int ti = li[k];
                if (better){ lv[k] = cvv; li[k] = cix; cvv = tv; cix = ti; }
            }
        }
        int ptr = 0;
        for (int r = 0; r < NPTS; r++){
            unsigned long long mykey = 0ULL;
            if (ptr < NPTS && lv[ptr] > -1e29f)
                mykey = ((unsigned long long)__float_as_uint(lv[ptr]) << 32)
                      | (unsigned int)(~(unsigned)li[ptr]);
            bestkey[tid] = mykey;
            __syncthreads();
            for (int st = 512; st > 0; st >>= 1){
                if (tid < st){
                    unsigned long long o = bestkey[tid+st];
                    if (o > bestkey[tid]) bestkey[tid] = o;
                }
                __syncthreads();
            }
            unsigned long long win = bestkey[0];
            if (tid == 0){ fbIdx[r] = (int)(~(unsigned)(win & 0xffffffffu)); sWin = win; }
            __syncthreads();
            if (mykey != 0ULL && mykey == sWin) ptr++;
            __syncthreads();
        }
    }

    if (tid < NPTS){
        int si = (tid < cnt) ? chosenIdx[tid] : fbIdx[tid - cnt];
        out[b*20 + tid*2 + 0] = (float)(si & (HS-1)) * (1.0f/512.0f);
        out[b*20 + tid*2 + 1] = (float)(si >> 9)     * (1.0f/512.0f);
        out[BATCH*NPTS*2 + b*NPTS + tid] = 1.0f;
    }
}

// ---------------- launch ----------------
extern "C" void kernel_launch(void* const* d_in, const int* in_sizes, int n_in,
                              void* d_out, int out_size){
    (void)in_sizes; (void)n_in; (void)out_size;
    const float* rgb = (const float*)d_in[0];
    const float* dep = (const float*)d_in[1];
    const float* w1  = (const float*)d_in[2];
    const float* b1  = (const float*)d_in[3];
    const float* gam = (const float*)d_in[4];
    const float* bet = (const float*)d_in[5];
    const float* mu  = (const float*)d_in[6];
    const float* var = (const float*)d_in[7];
    const float* w2  = (const float*)d_in[8];
    const float* b2  = (const float*)d_in[9];
    float* out = (float*)d_out;
    float* masks = out + (BATCH*NPTS*2 + BATCH*NPTS + BATCH*4);  // 272

    dim3 blk(32,8);
    kw_reorder<<<32, 256>>>(w1);
    void* wsrc = nullptr;
    cudaGetSymbolAddress(&wsrc, g_wre);
    cudaMemcpyToSymbolAsync(cW, wsrc, 3456*sizeof(float), 0, cudaMemcpyDeviceToDevice, 0);

    cudaFuncSetAttribute(k3_conv, cudaFuncAttributeMaxDynamicSharedMemorySize, K3_SMEM);
    cudaFuncSetAttribute(k3_conv, cudaFuncAttributePreferredSharedMemoryCarveout, 100);
    k3_conv<<<dim3(16,32,BATCH), 256, K3_SMEM>>>(rgb,dep,b1,gam,bet,mu,var,w2,b2);
    k45_mask_peaks<<<dim3(16,64,BATCH), blk>>>(masks);
    cudaFuncSetAttribute(k6_points, cudaFuncAttributeMaxDynamicSharedMemorySize, 86528);
    k6_points<<<2*BATCH, 1024, 86528>>>(out);
}

// round 13
// speedup vs baseline: 1.0717x; 1.0717x over previous
#include <cuda_runtime.h>
#include <math.h>

#define BATCH 8
#define HW 1024
#define HS 512
#define NPIX (HS*HS)
#define NPTS 10
#define KP 512
#define SORTN 8192
#define ER 22
#define EC 38

// ---------------- scratch (device globals; no allocation) ----------------
__device__ float g_sal[BATCH*NPIX];
__device__ float g_cand_val[BATCH*NPIX];
__device__ int   g_cand_idx[BATCH*NPIX];
__device__ int   g_cand_cnt[BATCH];
__device__ int   g_rowflag[BATCH*HW];
__device__ int   g_colflag[BATCH*HW];

// reordered conv1 weights: [(c*9+tap)*8 + q] = ulonglong2{oc 4q..4q+1, oc 4q+2..4q+3}
__device__ __align__(16) float g_wre[3456];
__constant__ __align__(16) ulonglong2 cW[864];

// ---------------- packed f32x2 helpers ----------------
__device__ __forceinline__ unsigned long long fma2(unsigned long long a,
                                                   unsigned long long b,
                                                   unsigned long long c){
    unsigned long long d;
    asm("fma.rn.f32x2 %0, %1, %2, %3;" : "=l"(d) : "l"(a), "l"(b), "l"(c));
    return d;
}
__device__ __forceinline__ unsigned long long pack2(float v){
    unsigned long long d;
    asm("mov.b64 %0, {%1, %1};" : "=l"(d) : "f"(v));
    return d;
}
__device__ __forceinline__ void unpack2(unsigned long long p, float& lo, float& hi){
    asm("mov.b64 {%0, %1}, %2;" : "=f"(lo), "=f"(hi) : "l"(p));
}

// inclusive suffix scan over 1024 values (one per thread), 2 barriers total
__device__ __forceinline__ int suffix_scan_1024(int v, int tid, int* warpbuf){
    int lane = tid & 31, w = tid >> 5;
    #pragma unroll
    for (int off = 1; off < 32; off <<= 1){
        int o = __shfl_down_sync(0xffffffffu, v, off);
        if (lane + off < 32) v += o;
    }
    if (lane == 0) warpbuf[w] = v;        // warp total sits in lane 0's v
    __syncthreads();
    if (w == 0){
        int s = warpbuf[lane];
        #pragma unroll
        for (int off = 1; off < 32; off <<= 1){
            int o = __shfl_down_sync(0xffffffffu, s, off);
            if (lane + off < 32) s += o;
        }
        warpbuf[lane] = s;                // suffix over warps, incl. own
    }
    __syncthreads();
    int later = (w < 31) ? warpbuf[w+1] : 0;
    return v + later;
}

// ---------------- KW: reorder conv1 weights + zero flags/counters ----------------
__global__ void kw_reorder(const float* __restrict__ w1){
    int l = blockIdx.x*256 + threadIdx.x;
    if (l < 3456){
        int tl = l >> 5, oc = l & 31;
        g_wre[tl*32 + oc] = w1[oc*108 + tl];
    }
    if (l < BATCH*HW){ g_rowflag[l] = 0; g_colflag[l] = 0; }
    if (l < BATCH) g_cand_cnt[l] = 0;
}

// ---------------- K3: fused DWT+energy+smooth+conv+BN+GELU+conv1x1+sigmoid ----------------
__global__ __launch_bounds__(256, 1) void k3_conv(
    const float* __restrict__ rgb, const float* __restrict__ dep,
    const float* __restrict__ b1,
    const float* __restrict__ gam, const float* __restrict__ bet,
    const float* __restrict__ mu,  const float* __restrict__ var,
    const float* __restrict__ w2,  const float* __restrict__ b2)
{
    __shared__ float sIn[12*18*34];          // 12 ch x (18 rows x 34 cols), halo 1
    __shared__ float sE[2*ER*EC];            // E_rgb, E_dep on 22x38 (halo 3)
    __shared__ float sH[2*ER*34];            // horizontally smoothed E
    __shared__ float sSc[32], sSh[32], sW2[32];
    __shared__ float sB2;
    int tid = threadIdx.x;
    int b = blockIdx.z;
    int ty0 = blockIdx.y*16, tx0 = blockIdx.x*32;

    // normalized separable gaussian (identical to former k2)
    const float e0 = 1.0f, e1 = 0.60653065971f, e2 = 0.13533528323f;
    const float sum1 = e0 + 2.f*e1 + 2.f*e2;
    const float w0 = e0/sum1, w1c = e1/sum1, w2c = e2/sum1;

    size_t plane = (size_t)HW*HW;
    const float* RP = rgb + (size_t)b*3*plane;
    const float* GP = RP + plane;
    const float* BP = GP + plane;
    const float* DP = dep + (size_t)b*plane;

    // ---- phase A: gray + Haar DWT + energy on the 22x38 halo region ----
    for (int l = tid; l < ER*EC; l += 256){
        int ey = l / EC, ex = l - ey*EC;
        int gy = ty0 - 3 + ey, gx = tx0 - 3 + ex;
        bool in = (gy >= 0 && gy < HS && gx >= 0 && gx < HS);
        float er = 0.f, ed = 0.f;
        float LLr=0.f,LHr=0.f,HLr=0.f,HHr=0.f, LLd=0.f,LHd=0.f,HLd=0.f,HHd=0.f;
        if (in){
            int i00 = (2*gy)*HW + 2*gx;
            int i01 = i00 + 1, i10 = i00 + HW, i11 = i00 + HW + 1;
            float v00 = (RP[i00]+GP[i00]+BP[i00])/3.0f;
            float v01 = (RP[i01]+GP[i01]+BP[i01])/3.0f;
            float v10 = (RP[i10]+GP[i10]+BP[i10])/3.0f;
            float v11 = (RP[i11]+GP[i11]+BP[i11])/3.0f;
            {
                float a=v00*0.5f, c2=v10*0.5f, e22=v01*0.5f, f2=v11*0.5f;
                LLr=a+c2; LHr=a-c2; HLr=e22+f2; HHr=e22-f2;
                er = sqrtf(LHr*LHr+HLr*HLr+HHr*HHr+1e-8f);
            }
            {
                float a=DP[i00]*0.5f, c2=DP[i10]*0.5f, e22=DP[i01]*0.5f, f2=DP[i11]*0.5f;
                LLd=a+c2; LHd=a-c2; HLd=e22+f2; HHd=e22-f2;
                ed = sqrtf(LHd*LHd+HLd*HLd+HHd*HHd+1e-8f);
            }
        }
        sE[l] = er; sE[ER*EC + l] = ed;
        int iy = ey - 2, ix = ex - 2;
        if (iy >= 0 && iy < 18 && ix >= 0 && ix < 34){
            int o = iy*34 + ix;
            sIn[0*612+o]=LLr; sIn[1*612+o]=LHr; sIn[2*612+o]=HLr; sIn[3*612+o]=HHr;
            sIn[4*612+o]=LLd; sIn[5*612+o]=LHd; sIn[6*612+o]=HLd; sIn[7*612+o]=HHd;
            sIn[8*612+o]=er;  sIn[9*612+o]=ed;
        }
    }
    if (tid < 32){
        float inv = 1.0f/sqrtf(var[tid] + 1e-5f);
        float sc = gam[tid]*inv;
        sSc[tid] = sc;
        sSh[tid] = (b1[tid] - mu[tid])*sc + bet[tid];
        sW2[tid] = w2[tid];
    }
    if (tid == 0) sB2 = b2[0];
    __syncthreads();

    // ---- phase B: horizontal smooth (identical formula to former k2) ----
    for (int l = tid; l < 2*ER*34; l += 256){
        int ch = l / (ER*34);
        int rr = l - ch*(ER*34);
        int r = rr/34, c = rr - r*34;
        const float* e = sE + ch*ER*EC + r*EC + c;
        sH[l] = w2c*(e[0]+e[4]) + w1c*(e[1]+e[3]) + w0*e[2];
    }
    __syncthreads();

    // ---- phase C: vertical smooth -> channels 10, 11 (ZERO outside image: conv pad) ----
    for (int l = tid; l < 2*612; l += 256){
        int ch = l / 612;
        int o = l - ch*612;
        int iy = o/34, ix = o - iy*34;
        int gy = ty0 + iy - 1, gx = tx0 + ix - 1;          // image coords of this sIn cell
        float v = 0.f;
        if (gy >= 0 && gy < HS && gx >= 0 && gx < HS){     // conv1 zero-padding
            const float* h = sH + ch*(ER*34) + iy*34 + ix;
            v = w2c*(h[0]+h[4*34]) + w1c*(h[1*34]+h[3*34]) + w0*h[2*34];
        }
        sIn[(10+ch)*612 + o] = v;
    }
    __syncthreads();

    // ---- mainloop: conv3x3(12->32), f32x2, weights in constant bank ----
    int ty = tid >> 5, tx = tid & 31;
    unsigned long long accA[16], accB[16];
    #pragma unroll
    for (int i=0;i<16;i++){ accA[i] = 0ULL; accB[i] = 0ULL; }
    for (int c=0; c<12; c++){
        #pragma unroll
        for (int tap=0; tap<9; tap++){
            int ky = tap/3, kx = tap%3;
            float a0 = sIn[c*612 + (ty+ky)*34 + (tx+kx)];
            float a1 = sIn[c*612 + (ty+8+ky)*34 + (tx+kx)];
            unsigned long long v0 = pack2(a0), v1 = pack2(a1);
            const ulonglong2* wrow = cW + (c*9+tap)*8;
            #pragma unroll
            for (int q=0;q<8;q++){
                ulonglong2 wp = wrow[q];
                accA[2*q+0] = fma2(v0, wp.x, accA[2*q+0]);
                accA[2*q+1] = fma2(v0, wp.y, accA[2*q+1]);
                accB[2*q+0] = fma2(v1, wp.x, accB[2*q+0]);
                accB[2*q+1] = fma2(v1, wp.y, accB[2*q+1]);
            }
        }
    }
    float zA = sB2, zB = sB2;
    #pragma unroll
    for (int j=0; j<16; j++){
        float a0, a1, b0, b1v;
        unpack2(accA[j], a0, a1);
        unpack2(accB[j], b0, b1v);
        int oc = 2*j;
        {
            float xv = fmaf(a0, sSc[oc], sSh[oc]);
            float gl = 0.5f*xv*(1.0f + tanhf(0.7978845608f*(xv + 0.044715f*xv*xv*xv)));
            zA = fmaf(gl, sW2[oc], zA);
        }
        {
            float xv = fmaf(a1, sSc[oc+1], sSh[oc+1]);
            float gl = 0.5f*xv*(1.0f + tanhf(0.7978845608f*(xv + 0.044715f*xv*xv*xv)));
            zA = fmaf(gl, sW2[oc+1], zA);
        }
        {
            float xv = fmaf(b0, sSc[oc], sSh[oc]);
            float gl = 0.5f*xv*(1.0f + tanhf(0.7978845608f*(xv + 0.044715f*xv*xv*xv)));
            zB = fmaf(gl, sW2[oc], zB);
        }
        {
            float xv = fmaf(b1v, sSc[oc+1], sSh[oc+1]);
            float gl = 0.5f*xv*(1.0f + tanhf(0.7978845608f*(xv + 0.044715f*xv*xv*xv)));
            zB = fmaf(gl, sW2[oc+1], zB);
        }
    }
    float* S = g_sal + (size_t)b*NPIX;
    S[(ty0+ty)*HS + (tx0+tx)]     = 1.0f/(1.0f + expf(-zA));
    S[(ty0+ty+8)*HS + (tx0+tx)]   = 1.0f/(1.0f + expf(-zB));
}

// ---------------- K45: fused bilinear x2 upsample + flags + peaks ----------------
__global__ void k45_mask_peaks(float* __restrict__ masks){
    __shared__ int colAny[64];
    __shared__ int rowAny[16];
    __shared__ float sv[256];
    __shared__ int   si[256];
    __shared__ int   scnt, sbase;
    int tx = threadIdx.x, ty = threadIdx.y;
    int tid = ty*32 + tx;
    if (tid < 64) colAny[tid] = 0;
    if (tid < 16) rowAny[tid] = 0;
    if (tid == 0) scnt = 0;
    __syncthreads();
    int x = blockIdx.x*32 + tx;
    int y = blockIdx.y*8  + ty;
    int b = blockIdx.z;
    const float* s = g_sal + (size_t)b*NPIX;
    int xm = max(x-1,0), xp = min(x+1,HS-1);
    int ym = max(y-1,0), yp = min(y+1,HS-1);
    float n00=s[ym*HS+xm], n01=s[ym*HS+x], n02=s[ym*HS+xp];
    float n10=s[y*HS+xm],  v  =s[y*HS+x],  n12=s[y*HS+xp];
    float n20=s[yp*HS+xm], n21=s[yp*HS+x], n22=s[yp*HS+xp];
    float mp = fmaxf(fmaxf(fmaxf(n00,n01),fmaxf(n02,n10)),
                     fmaxf(fmaxf(v,n12),fmaxf(fmaxf(n20,n21),n22)));
    bool pk = (v == mp) && (v > 0.f);
    if (pk){
        int p = atomicAdd(&scnt, 1);
        sv[p] = v; si[p] = y*HS + x;
    }
    float m00 = 0.25f*(0.25f*n00 + 0.75f*n01) + 0.75f*(0.25f*n10 + 0.75f*v);
    float m01 = 0.25f*(0.75f*n01 + 0.25f*n02) + 0.75f*(0.75f*v + 0.25f*n12);
    float m10 = 0.75f*(0.25f*n10 + 0.75f*v)   + 0.25f*(0.25f*n20 + 0.75f*n21);
    float m11 = 0.75f*(0.75f*v + 0.25f*n12)   + 0.25f*(0.75f*n21 + 0.25f*n22);
    float* M = masks + (size_t)b*HW*HW;
    *(float2*)&M[(size_t)(2*y)*HW   + 2*x] = make_float2(m00, m01);
    *(float2*)&M[(size_t)(2*y+1)*HW + 2*x] = make_float2(m10, m11);
    bool r0 = (m00 > 0.5f) || (m01 > 0.5f);
    bool r1 = (m10 > 0.5f) || (m11 > 0.5f);
    bool c0 = (m00 > 0.5f) || (m10 > 0.5f);
    bool c1 = (m01 > 0.5f) || (m11 > 0.5f);
    if (r0) rowAny[2*ty] = 1;
    if (r1) rowAny[2*ty+1] = 1;
    if (c0) colAny[2*tx] = 1;
    if (c1) colAny[2*tx+1] = 1;
    __syncthreads();
    if (tid < 16 && rowAny[tid]) atomicOr(&g_rowflag[b*HW + blockIdx.y*16 + tid], 1);
    if (tid < 64 && colAny[tid]) atomicOr(&g_colflag[b*HW + blockIdx.x*64 + tid], 1);
    if (tid == 0 && scnt) sbase = atomicAdd(&g_cand_cnt[b], scnt);
    __syncthreads();
    if (tid < scnt){
        g_cand_val[(size_t)b*NPIX + sbase + tid] = sv[tid];
        g_cand_idx[(size_t)b*NPIX + sbase + tid] = si[tid];
    }
}

// ---------------- K6: points (blocks 0..7) + boxes (blocks 8..15) ----------------
__global__ __launch_bounds__(1024) void k6_points(float* __restrict__ out){
    extern __shared__ unsigned char sraw[];
    int tid = threadIdx.x;

    if (blockIdx.x >= BATCH){
        int b = blockIdx.x - BATCH;
        int* sred = (int*)sraw;
        int rf = g_rowflag[b*HW + tid];
        int cf = g_colflag[b*HW + tid];
        int res[4];
        int init[4] = { rf ? tid : HW, rf ? tid : -1, cf ? tid : HW, cf ? tid : -1 };
        #pragma unroll
        for (int w = 0; w < 4; w++){
            sred[tid] = init[w];
            __syncthreads();
            for (int st = 512; st > 0; st >>= 1){
                if (tid < st){
                    int o = sred[tid+st];
                    sred[tid] = (w == 0 || w == 2) ? min(sred[tid], o) : max(sred[tid], o);
                }
                __syncthreads();
            }
            res[w] = sred[0];
            __syncthreads();
        }
        if (tid == 0){
            float* bx = out + BATCH*NPTS*2 + BATCH*NPTS + b*4;
            if (res[1] >= 0){ bx[0]=(float)res[2]; bx[1]=(float)res[0]; bx[2]=(float)res[3]; bx[3]=(float)res[1]; }
            else            { bx[0]=0.f; bx[1]=0.f; bx[2]=(float)(HW-1); bx[3]=(float)(HW-1); }
        }
        return;
    }

    unsigned long long* keys = (unsigned long long*)sraw;
    unsigned int* hist = (unsigned int*)(sraw + 65536);
    unsigned long long* bestkey = (unsigned long long*)(sraw + 65536);
    unsigned char* avail = (unsigned char*)(sraw + 86016);
    __shared__ int warpbuf[32];
    __shared__ int s_ti[KP];
    __shared__ int sT, sTf, sM, sChi, sCnt, sPick, sCur;
    __shared__ int chosenIdx[NPTS];
    __shared__ int fbIdx[NPTS];
    __shared__ unsigned long long sWin;

    int b = blockIdx.x;
    int N = g_cand_cnt[b];
    if (N > NPIX) N = NPIX;
    int need = min(KP, N);
    const float* cv = g_cand_val + (size_t)b*NPIX;
    const int*   ci = g_cand_idx + (size_t)b*NPIX;

    hist[tid] = 0u; hist[tid+1024] = 0u; hist[tid+2048] = 0u; hist[tid+3072] = 0u;
    if (tid == 0){ sT = 0; sM = 0; sChi = 0; sTf = 0; }
    __syncthreads();
    for (int i = tid; i < N; i += 1024){
        int bin = max(0, min(4095, (int)(cv[i]*4096.0f)));
        atomicAdd(&hist[bin], 1u);
    }
    __syncthreads();
    int t4 = tid*4;
    {
        int h0 = hist[t4], h1 = hist[t4+1], h2 = hist[t4+2], h3 = hist[t4+3];
        int base = suffix_scan_1024(h0+h1+h2+h3, tid, warpbuf);  // sum bins >= t4
        int s1 = base - h0, s2 = s1 - h1, s3 = s2 - h2;
        int bestT = -1;
        if (s3 >= need) bestT = t4+3;
        else if (s2 >= need) bestT = t4+2;
        else if (s1 >= need) bestT = t4+1;
        else if (base >= need) bestT = t4;
        if (bestT >= 0) atomicMax(&sT, bestT);
    }
    __syncthreads();
    int T = sT;
    hist[tid] = 0u; hist[tid+1024] = 0u; hist[tid+2048] = 0u; hist[tid+3072] = 0u;
    __syncthreads();
    for (int i = tid; i < N; i += 1024){
        float v = cv[i];
        int bin = max(0, min(4095, (int)(v*4096.0f)));
        if (bin > T) atomicAdd(&sChi, 1);
        else if (bin == T){
            float frac = v*4096.0f - (float)T;
            int fb = max(0, min(4095, (int)(frac*4096.0f)));
            atomicAdd(&hist[fb], 1u);
        }
    }
    __syncthreads();
    int needF = need - sChi;
    {
        int h0 = hist[t4], h1 = hist[t4+1], h2 = hist[t4+2], h3 = hist[t4+3];
        int base = suffix_scan_1024(h0+h1+h2+h3, tid, warpbuf);
        int s1 = base - h0, s2 = s1 - h1, s3 = s2 - h2;
        int bestT = -1;
        if (s3 >= needF) bestT = t4+3;
        else if (s2 >= needF) bestT = t4+2;
        else if (s1 >= needF) bestT = t4+1;
        else if (base >= needF) bestT = t4;
        if (bestT >= 0) atomicMax(&sTf, bestT);
    }
    __syncthreads();
    int Tf = sTf;
    for (int i = tid; i < N; i += 1024){
        float v = cv[i];
        int bin = max(0, min(4095, (int)(v*4096.0f)));
        bool take = (bin > T);
        if (!take && bin == T){
            float frac = v*4096.0f - (float)T;
            int fb = max(0, min(4095, (int)(frac*4096.0f)));
            take = (fb >= Tf);
        }
        if (take){
            int p = atomicAdd(&sM, 1);
            if (p < SORTN)
                keys[p] = ((unsigned long long)__float_as_uint(v) << 32)
                        | (unsigned int)(~(unsigned)ci[i]);
        }
    }
    __syncthreads();
    int M = min(sM, SORTN);
    int S = 512;
    while (S < M) S <<= 1;
    for (int i = M + tid; i < S; i += 1024) keys[i] = 0ULL;
    __syncthreads();
    for (int k = 2; k <= S; k <<= 1){
        for (int j = k >> 1; j > 0; j >>= 1){
            for (int i = tid; i < S; i += 1024){
                int ixj = i ^ j;
                if (ixj > i){
                    unsigned long long a = keys[i], c = keys[ixj];
                    bool up = ((i & k) == 0);
                    if ((a > c) == up){ keys[i] = c; keys[ixj] = a; }
                }
            }
            __syncthreads();
        }
    }
    if (tid < KP){
        s_ti[tid] = (int)(~(unsigned)(keys[S-1-tid] & 0xffffffffu));
        avail[tid] = 1;
    }
    __syncthreads();

    int Kv = min(N, KP);
    if (tid == 0){ sCnt = 0; sCur = 0; }
    __syncthreads();
    for (int round = 0; round < NPTS; round++){
        if (tid == 0){
            int i = sCur;
            while (i < Kv && !avail[i]) i++;
            if (i < Kv){
                chosenIdx[sCnt] = s_ti[i];
                sCnt++;
                sPick = i;
                sCur = i + 1;
            } else sPick = -1;
        }
        __syncthreads();
        int i = sPick;
        if (i < 0) break;
        int idx = s_ti[i];
        int xi = idx & (HS-1), yi = idx >> 9;
        if (tid < KP && tid > i && tid < Kv && avail[tid]){
            int dx = (s_ti[tid] & (HS-1)) - xi;
            int dy = (s_ti[tid] >> 9) - yi;
            if (dx*dx + dy*dy < 625) avail[tid] = 0;
        }
        __syncthreads();
    }
    int cnt = sCnt;

    if (cnt < NPTS){
        const float* s = g_sal + (size_t)b*NPIX;
        float lv[NPTS]; int li[NPTS];
        #pragma unroll
        for (int k=0;k<NPTS;k++){ lv[k] = -1e30f; li[k] = 0x7fffffff; }
        for (int p = tid; p < NPIX; p += 1024){
            float v = s[p];
            if (v <= lv[NPTS-1]) continue;
            int y = p >> 9, x = p & (HS-1);
            float mp = v;
            #pragma unroll
            for (int dy=-1; dy<=1; dy++){
                int yy = y + dy; if (yy < 0 || yy >= HS) continue;
                #pragma unroll
                for (int dx=-1; dx<=1; dx++){
                    int xx = x + dx; if (xx < 0 || xx >= HS) continue;
                    mp = fmaxf(mp, s[yy*HS + xx]);
                }
            }
            if (v == mp) continue;
            float cvv = v; int cix = p;
            #pragma unroll
            for (int k=0;k<NPTS;k++){
                bool better = (cvv > lv[k]) || (cvv == lv[k] && cix < li[k]);
                float tv = lv[k]; int ti = li[k];
                if (better){ lv[k] = cvv; li[k] = cix; cvv = tv; cix = ti; }
            }
        }
        int ptr = 0;
        for (int r = 0; r < NPTS; r++){
            unsigned long long mykey = 0ULL;
            if (ptr < NPTS && lv[ptr] > -1e29f)
                mykey = ((unsigned long long)__float_as_uint(lv[ptr]) << 32)
                      | (unsigned int)(~(unsigned)li[ptr]);
            bestkey[tid] = mykey;
            __syncthreads();
            for (int st = 512; st > 0; st >>= 1){
                if (tid < st){
                    unsigned long long o = bestkey[tid+st];
                    if (o > bestkey[tid]) bestkey[tid] = o;
                }
                __syncthreads();
            }
            unsigned long long win = bestkey[0];
            if (tid == 0){ fbIdx[r] = (int)(~(unsigned)(win & 0xffffffffu)); sWin = win; }
            __syncthreads();
            if (mykey != 0ULL && mykey == sWin) ptr++;
            __syncthreads();
        }
    }

    if (tid < NPTS){
        int si = (tid < cnt) ? chosenIdx[tid] : fbIdx[tid - cnt];
        out[b*20 + tid*2 + 0] = (float)(si & (HS-1)) * (1.0f/512.0f);
        out[b*20 + tid*2 + 1] = (float)(si >> 9)     * (1.0f/512.0f);
        out[BATCH*NPTS*2 + b*NPTS + tid] = 1.0f;
    }
}

// ---------------- launch ----------------
extern "C" void kernel_launch(void* const* d_in, const int* in_sizes, int n_in,
                              void* d_out, int out_size){
    (void)in_sizes; (void)n_in; (void)out_size;
    const float* rgb = (const float*)d_in[0];
    const float* dep = (const float*)d_in[1];
    const float* w1  = (const float*)d_in[2];
    const float* b1  = (const float*)d_in[3];
    const float* gam = (const float*)d_in[4];
    const float* bet = (const float*)d_in[5];
    const float* mu  = (const float*)d_in[6];
    const float* var = (const float*)d_in[7];
    const float* w2  = (const float*)d_in[8];
    const float* b2  = (const float*)d_in[9];
    float* out = (float*)d_out;
    float* masks = out + (BATCH*NPTS*2 + BATCH*NPTS + BATCH*4);  // 272

    dim3 blk(32,8);
    kw_reorder<<<32, 256>>>(w1);
    void* wsrc = nullptr;
    cudaGetSymbolAddress(&wsrc, g_wre);
    cudaMemcpyToSymbolAsync(cW, wsrc, 3456*sizeof(float), 0, cudaMemcpyDeviceToDevice, 0);

    k3_conv<<<dim3(16,32,BATCH), 256>>>(rgb,dep,b1,gam,bet,mu,var,w2,b2);
    k45_mask_peaks<<<dim3(16,64,BATCH), blk>>>(masks);
    cudaFuncSetAttribute(k6_points, cudaFuncAttributeMaxDynamicSharedMemorySize, 86528);
    k6_points<<<2*BATCH, 1024, 86528>>>(out);
}

// round 14
// speedup vs baseline: 1.0764x; 1.0044x over previous
#include <cuda_runtime.h>
#include <math.h>

#define BATCH 8
#define HW 1024
#define HS 512
#define NPIX (HS*HS)
#define NPTS 10
#define KP 512
#define SORTN 8192
#define ER 22
#define EC 38

// ---------------- scratch (device globals; no allocation) ----------------
__device__ float g_sal[BATCH*NPIX];
__device__ float g_cand_val[BATCH*NPIX];
__device__ int   g_cand_idx[BATCH*NPIX];
__device__ int   g_cand_cnt[BATCH];
__device__ int   g_rowflag[BATCH*HW];
__device__ int   g_colflag[BATCH*HW];

// reordered conv1 weights: [(c*9+tap)*8 + q] = ulonglong2{oc 4q..4q+1, oc 4q+2..4q+3}
__device__ __align__(16) float g_wre[3456];
__constant__ __align__(16) ulonglong2 cW[864];

// ---------------- packed f32x2 helpers ----------------
__device__ __forceinline__ unsigned long long fma2(unsigned long long a,
                                                   unsigned long long b,
                                                   unsigned long long c){
    unsigned long long d;
    asm("fma.rn.f32x2 %0, %1, %2, %3;" : "=l"(d) : "l"(a), "l"(b), "l"(c));
    return d;
}
__device__ __forceinline__ unsigned long long pack2(float v){
    unsigned long long d;
    asm("mov.b64 %0, {%1, %1};" : "=l"(d) : "f"(v));
    return d;
}
__device__ __forceinline__ void unpack2(unsigned long long p, float& lo, float& hi){
    asm("mov.b64 {%0, %1}, %2;" : "=f"(lo), "=f"(hi) : "l"(p));
}

// inclusive suffix scan over 1024 values (one per thread), 2 barriers total
__device__ __forceinline__ int suffix_scan_1024(int v, int tid, int* warpbuf){
    int lane = tid & 31, w = tid >> 5;
    #pragma unroll
    for (int off = 1; off < 32; off <<= 1){
        int o = __shfl_down_sync(0xffffffffu, v, off);
        if (lane + off < 32) v += o;
    }
    if (lane == 0) warpbuf[w] = v;
    __syncthreads();
    if (w == 0){
        int s = warpbuf[lane];
        #pragma unroll
        for (int off = 1; off < 32; off <<= 1){
            int o = __shfl_down_sync(0xffffffffu, s, off);
            if (lane + off < 32) s += o;
        }
        warpbuf[lane] = s;
    }
    __syncthreads();
    int later = (w < 31) ? warpbuf[w+1] : 0;
    return v + later;
}

// ---------------- KW: reorder conv1 weights + zero flags/counters ----------------
__global__ void kw_reorder(const float* __restrict__ w1){
    int l = blockIdx.x*256 + threadIdx.x;
    if (l < 3456){
        int tl = l >> 5, oc = l & 31;
        g_wre[tl*32 + oc] = w1[oc*108 + tl];
    }
    if (l < BATCH*HW){ g_rowflag[l] = 0; g_colflag[l] = 0; }
    if (l < BATCH) g_cand_cnt[l] = 0;
}

// ---------------- K3: fused DWT+energy+smooth+conv+BN+GELU+conv1x1+sigmoid ----------------
__global__ __launch_bounds__(256, 1) void k3_conv(
    const float* __restrict__ rgb, const float* __restrict__ dep,
    const float* __restrict__ b1,
    const float* __restrict__ gam, const float* __restrict__ bet,
    const float* __restrict__ mu,  const float* __restrict__ var,
    const float* __restrict__ w2,  const float* __restrict__ b2)
{
    __shared__ float sIn[12*18*34];          // 12 ch x (18 rows x 34 cols), halo 1
    __shared__ float sE[2*ER*EC];            // E_rgb, E_dep on 22x38 (halo 3)
    __shared__ float sH[2*ER*34];            // horizontally smoothed E
    __shared__ float sSc[32], sSh[32], sW2[32];
    __shared__ float sB2;
    int tid = threadIdx.x;
    int b = blockIdx.z;
    int ty0 = blockIdx.y*16, tx0 = blockIdx.x*32;

    const float e0 = 1.0f, e1 = 0.60653065971f, e2 = 0.13533528323f;
    const float sum1 = e0 + 2.f*e1 + 2.f*e2;
    const float w0 = e0/sum1, w1c = e1/sum1, w2c = e2/sum1;

    size_t plane = (size_t)HW*HW;
    const float* RP = rgb + (size_t)b*3*plane;
    const float* GP = RP + plane;
    const float* BP = GP + plane;
    const float* DP = dep + (size_t)b*plane;

    // ---- phase A: gray + Haar DWT + energy on the 22x38 halo region ----
    for (int l = tid; l < ER*EC; l += 256){
        int ey = l / EC, ex = l - ey*EC;
        int gy = ty0 - 3 + ey, gx = tx0 - 3 + ex;
        bool in = (gy >= 0 && gy < HS && gx >= 0 && gx < HS);
        float er = 0.f, ed = 0.f;
        float LLr=0.f,LHr=0.f,HLr=0.f,HHr=0.f, LLd=0.f,LHd=0.f,HLd=0.f,HHd=0.f;
        if (in){
            int i00 = (2*gy)*HW + 2*gx;
            int i01 = i00 + 1, i10 = i00 + HW, i11 = i00 + HW + 1;
            float v00 = (RP[i00]+GP[i00]+BP[i00])/3.0f;
            float v01 = (RP[i01]+GP[i01]+BP[i01])/3.0f;
            float v10 = (RP[i10]+GP[i10]+BP[i10])/3.0f;
            float v11 = (RP[i11]+GP[i11]+BP[i11])/3.0f;
            {
                float a=v00*0.5f, c2=v10*0.5f, e22=v01*0.5f, f2=v11*0.5f;
                LLr=a+c2; LHr=a-c2; HLr=e22+f2; HHr=e22-f2;
                er = sqrtf(LHr*LHr+HLr*HLr+HHr*HHr+1e-8f);
            }
            {
                float a=DP[i00]*0.5f, c2=DP[i10]*0.5f, e22=DP[i01]*0.5f, f2=DP[i11]*0.5f;
                LLd=a+c2; LHd=a-c2; HLd=e22+f2; HHd=e22-f2;
                ed = sqrtf(LHd*LHd+HLd*HLd+HHd*HHd+1e-8f);
            }
        }
        sE[l] = er; sE[ER*EC + l] = ed;
        int iy = ey - 2, ix = ex - 2;
        if (iy >= 0 && iy < 18 && ix >= 0 && ix < 34){
            int o = iy*34 + ix;
            sIn[0*612+o]=LLr; sIn[1*612+o]=LHr; sIn[2*612+o]=HLr; sIn[3*612+o]=HHr;
            sIn[4*612+o]=LLd; sIn[5*612+o]=LHd; sIn[6*612+o]=HLd; sIn[7*612+o]=HHd;
            sIn[8*612+o]=er;  sIn[9*612+o]=ed;
        }
    }
    if (tid < 32){
        float inv = 1.0f/sqrtf(var[tid] + 1e-5f);
        float sc = gam[tid]*inv;
        sSc[tid] = sc;
        sSh[tid] = (b1[tid] - mu[tid])*sc + bet[tid];
        sW2[tid] = w2[tid];
    }
    if (tid == 0) sB2 = b2[0];
    __syncthreads();

    // ---- phase B: horizontal smooth ----
    for (int l = tid; l < 2*ER*34; l += 256){
        int ch = l / (ER*34);
        int rr = l - ch*(ER*34);
        int r = rr/34, c = rr - r*34;
        const float* e = sE + ch*ER*EC + r*EC + c;
        sH[l] = w2c*(e[0]+e[4]) + w1c*(e[1]+e[3]) + w0*e[2];
    }
    __syncthreads();

    // ---- phase C: vertical smooth -> channels 10, 11 (ZERO outside image: conv pad) ----
    for (int l = tid; l < 2*612; l += 256){
        int ch = l / 612;
        int o = l - ch*612;
        int iy = o/34, ix = o - iy*34;
        int gy = ty0 + iy - 1, gx = tx0 + ix - 1;
        float v = 0.f;
        if (gy >= 0 && gy < HS && gx >= 0 && gx < HS){
            const float* h = sH + ch*(ER*34) + iy*34 + ix;
            v = w2c*(h[0]+h[4*34]) + w1c*(h[1*34]+h[3*34]) + w0*h[2*34];
        }
        sIn[(10+ch)*612 + o] = v;
    }
    __syncthreads();

    // ---- mainloop: conv3x3(12->32), f32x2, weights in constant bank ----
    int ty = tid >> 5, tx = tid & 31;
    unsigned long long accA[16], accB[16];
    #pragma unroll
    for (int i=0;i<16;i++){ accA[i] = 0ULL; accB[i] = 0ULL; }
    for (int c=0; c<12; c++){
        #pragma unroll
        for (int tap=0; tap<9; tap++){
            int ky = tap/3, kx = tap%3;
            float a0 = sIn[c*612 + (ty+ky)*34 + (tx+kx)];
            float a1 = sIn[c*612 + (ty+8+ky)*34 + (tx+kx)];
            unsigned long long v0 = pack2(a0), v1 = pack2(a1);
            const ulonglong2* wrow = cW + (c*9+tap)*8;
            #pragma unroll
            for (int q=0;q<8;q++){
                ulonglong2 wp = wrow[q];
                accA[2*q+0] = fma2(v0, wp.x, accA[2*q+0]);
                accA[2*q+1] = fma2(v0, wp.y, accA[2*q+1]);
                accB[2*q+0] = fma2(v1, wp.x, accB[2*q+0]);
                accB[2*q+1] = fma2(v1, wp.y, accB[2*q+1]);
            }
        }
    }
    float zA = sB2, zB = sB2;
    #pragma unroll
    for (int j=0; j<16; j++){
        float a0, a1, b0, b1v;
        unpack2(accA[j], a0, a1);
        unpack2(accB[j], b0, b1v);
        int oc = 2*j;
        {
            float xv = fmaf(a0, sSc[oc], sSh[oc]);
            float gl = 0.5f*xv*(1.0f + tanhf(0.7978845608f*(xv + 0.044715f*xv*xv*xv)));
            zA = fmaf(gl, sW2[oc], zA);
        }
        {
            float xv = fmaf(a1, sSc[oc+1], sSh[oc+1]);
            float gl = 0.5f*xv*(1.0f + tanhf(0.7978845608f*(xv + 0.044715f*xv*xv*xv)));
            zA = fmaf(gl, sW2[oc+1], zA);
        }
        {
            float xv = fmaf(b0, sSc[oc], sSh[oc]);
            float gl = 0.5f*xv*(1.0f + tanhf(0.7978845608f*(xv + 0.044715f*xv*xv*xv)));
            zB = fmaf(gl, sW2[oc], zB);
        }
        {
            float xv = fmaf(b1v, sSc[oc+1], sSh[oc+1]);
            float gl = 0.5f*xv*(1.0f + tanhf(0.7978845608f*(xv + 0.044715f*xv*xv*xv)));
            zB = fmaf(gl, sW2[oc+1], zB);
        }
    }
    float* S = g_sal + (size_t)b*NPIX;
    S[(ty0+ty)*HS + (tx0+tx)]     = 1.0f/(1.0f + expf(-zA));
    S[(ty0+ty+8)*HS + (tx0+tx)]   = 1.0f/(1.0f + expf(-zB));
}

// ---------------- K45: smem-tiled bilinear x2 upsample + flags + peaks, 2 px/thread ----------------
// block covers a 32x16 sal tile; smem tile 18x34 with border-CLAMPED halo
__global__ void k45_mask_peaks(float* __restrict__ masks){
    __shared__ float sS[18*34];
    __shared__ int colAny[64];
    __shared__ int rowAny[32];
    __shared__ float sv[512];
    __shared__ int   si[512];
    __shared__ int   scnt, sbase;
    int tx = threadIdx.x, ty = threadIdx.y;
    int tid = ty*32 + tx;
    int ty0 = blockIdx.y*16, tx0 = blockIdx.x*32;
    int b = blockIdx.z;
    const float* s = g_sal + (size_t)b*NPIX;
    // load clamped tile
    for (int l = tid; l < 612; l += 256){
        int iy = l/34, ix = l - iy*34;
        int gy = min(max(ty0 + iy - 1, 0), HS-1);
        int gx = min(max(tx0 + ix - 1, 0), HS-1);
        sS[l] = s[gy*HS + gx];
    }
    if (tid < 64) colAny[tid] = 0;
    if (tid < 32) rowAny[tid] = 0;
    if (tid == 0) scnt = 0;
    __syncthreads();

    float* M = masks + (size_t)b*HW*HW;
    #pragma unroll
    for (int k = 0; k < 2; k++){
        int ly = ty + 8*k;               // local sal row 0..15
        int y  = ty0 + ly;
        int x  = tx0 + tx;
        const float* r0 = sS + ly*34 + tx;
        float n00=r0[0],  n01=r0[1],  n02=r0[2];
        float n10=r0[34], v  =r0[35], n12=r0[36];
        float n20=r0[68], n21=r0[69], n22=r0[70];
        // peak detection (clamped duplicates can't exceed in-window max)
        float mp = fmaxf(fmaxf(fmaxf(n00,n01),fmaxf(n02,n10)),
                         fmaxf(fmaxf(v,n12),fmaxf(fmaxf(n20,n21),n22)));
        bool pk = (v == mp) && (v > 0.f);
        if (pk){
            int p = atomicAdd(&scnt, 1);
            sv[p] = v; si[p] = y*HS + x;
        }
        // bilinear x2
        float m00 = 0.25f*(0.25f*n00 + 0.75f*n01) + 0.75f*(0.25f*n10 + 0.75f*v);
        float m01 = 0.25f*(0.75f*n01 + 0.25f*n02) + 0.75f*(0.75f*v + 0.25f*n12);
        float m10 = 0.75f*(0.25f*n10 + 0.75f*v)   + 0.25f*(0.25f*n20 + 0.75f*n21);
        float m11 = 0.75f*(0.75f*v + 0.25f*n12)   + 0.25f*(0.75f*n21 + 0.25f*n22);
        *(float2*)&M[(size_t)(2*y)*HW   + 2*x] = make_float2(m00, m01);
        *(float2*)&M[(size_t)(2*y+1)*HW + 2*x] = make_float2(m10, m11);
        bool r0f = (m00 > 0.5f) || (m01 > 0.5f);
        bool r1f = (m10 > 0.5f) || (m11 > 0.5f);
        bool c0f = (m00 > 0.5f) || (m10 > 0.5f);
        bool c1f = (m01 > 0.5f) || (m11 > 0.5f);
        if (r0f) rowAny[2*ly]   = 1;
        if (r1f) rowAny[2*ly+1] = 1;
        if (c0f) colAny[2*tx]   = 1;
        if (c1f) colAny[2*tx+1] = 1;
    }
    __syncthreads();
    if (tid < 32 && rowAny[tid]) atomicOr(&g_rowflag[b*HW + blockIdx.y*32 + tid], 1);
    if (tid < 64 && colAny[tid]) atomicOr(&g_colflag[b*HW + blockIdx.x*64 + tid], 1);
    if (tid == 0 && scnt) sbase = atomicAdd(&g_cand_cnt[b], scnt);
    __syncthreads();
    for (int p = tid; p < scnt; p += 256){
        g_cand_val[(size_t)b*NPIX + sbase + p] = sv[p];
        g_cand_idx[(size_t)b*NPIX + sbase + p] = si[p];
    }
}

// ---------------- K6: points (blocks 0..7) + boxes (blocks 8..15) ----------------
__global__ __launch_bounds__(1024) void k6_points(float* __restrict__ out){
    extern __shared__ unsigned char sraw[];
    int tid = threadIdx.x;

    if (blockIdx.x >= BATCH){
        int b = blockIdx.x - BATCH;
        int* sred = (int*)sraw;
        int rf = g_rowflag[b*HW + tid];
        int cf = g_colflag[b*HW + tid];
        int res[4];
        int init[4] = { rf ? tid : HW, rf ? tid : -1, cf ? tid : HW, cf ? tid : -1 };
        #pragma unroll
        for (int w = 0; w < 4; w++){
            sred[tid] = init[w];
            __syncthreads();
            for (int st = 512; st > 0; st >>= 1){
                if (tid < st){
                    int o = sred[tid+st];
                    sred[tid] = (w == 0 || w == 2) ? min(sred[tid], o) : max(sred[tid], o);
                }
                __syncthreads();
            }
            res[w] = sred[0];
            __syncthreads();
        }
        if (tid == 0){
            float* bx = out + BATCH*NPTS*2 + BATCH*NPTS + b*4;
            if (res[1] >= 0){ bx[0]=(float)res[2]; bx[1]=(float)res[0]; bx[2]=(float)res[3]; bx[3]=(float)res[1]; }
            else            { bx[0]=0.f; bx[1]=0.f; bx[2]=(float)(HW-1); bx[3]=(float)(HW-1); }
        }
        return;
    }

    unsigned long long* keys = (unsigned long long*)sraw;
    unsigned int* hist = (unsigned int*)(sraw + 65536);
    unsigned long long* bestkey = (unsigned long long*)(sraw + 65536);
    unsigned char* avail = (unsigned char*)(sraw + 86016);
    __shared__ int warpbuf[32];
    __shared__ int s_ti[KP];
    __shared__ int sT, sTf, sM, sChi, sCnt, sPick, sCur;
    __shared__ int chosenIdx[NPTS];
    __shared__ int fbIdx[NPTS];
    __shared__ unsigned long long sWin;

    int b = blockIdx.x;
    int N = g_cand_cnt[b];
    if (N > NPIX) N = NPIX;
    int need = min(KP, N);
    const float* cv = g_cand_val + (size_t)b*NPIX;
    const int*   ci = g_cand_idx + (size_t)b*NPIX;

    hist[tid] = 0u; hist[tid+1024] = 0u; hist[tid+2048] = 0u; hist[tid+3072] = 0u;
    if (tid == 0){ sT = 0; sM = 0; sChi = 0; sTf = 0; }
    __syncthreads();
    for (int i = tid; i < N; i += 1024){
        int bin = max(0, min(4095, (int)(cv[i]*4096.0f)));
        atomicAdd(&hist[bin], 1u);
    }
    __syncthreads();
    int t4 = tid*4;
    {
        int h0 = hist[t4], h1 = hist[t4+1], h2 = hist[t4+2], h3 = hist[t4+3];
        int base = suffix_scan_1024(h0+h1+h2+h3, tid, warpbuf);
        int s1 = base - h0, s2 = s1 - h1, s3 = s2 - h2;
        int bestT = -1;
        if (s3 >= need) bestT = t4+3;
        else if (s2 >= need) bestT = t4+2;
        else if (s1 >= need) bestT = t4+1;
        else if (base >= need) bestT = t4;
        if (bestT >= 0) atomicMax(&sT, bestT);
    }
    __syncthreads();
    int T = sT;
    hist[tid] = 0u; hist[tid+1024] = 0u; hist[tid+2048] = 0u; hist[tid+3072] = 0u;
    __syncthreads();
    for (int i = tid; i < N; i += 1024){
        float v = cv[i];
        int bin = max(0, min(4095, (int)(v*4096.0f)));
        if (bin > T) atomicAdd(&sChi, 1);
        else if (bin == T){
            float frac = v*4096.0f - (float)T;
            int fb = max(0, min(4095, (int)(frac*4096.0f)));
            atomicAdd(&hist[fb], 1u);
        }
    }
    __syncthreads();
    int needF = need - sChi;
    {
        int h0 = hist[t4], h1 = hist[t4+1], h2 = hist[t4+2], h3 = hist[t4+3];
        int base = suffix_scan_1024(h0+h1+h2+h3, tid, warpbuf);
        int s1 = base - h0, s2 = s1 - h1, s3 = s2 - h2;
        int bestT = -1;
        if (s3 >= needF) bestT = t4+3;
        else if (s2 >= needF) bestT = t4+2;
        else if (s1 >= needF) bestT = t4+1;
        else if (base >= needF) bestT = t4;
        if (bestT >= 0) atomicMax(&sTf, bestT);
    }
    __syncthreads();
    int Tf = sTf;
    for (int i = tid; i < N; i += 1024){
        float v = cv[i];
        int bin = max(0, min(4095, (int)(v*4096.0f)));
        bool take = (bin > T);
        if (!take && bin == T){
            float frac = v*4096.0f - (float)T;
            int fb = max(0, min(4095, (int)(frac*4096.0f)));
            take = (fb >= Tf);
        }
        if (take){
            int p = atomicAdd(&sM, 1);
            if (p < SORTN)
                keys[p] = ((unsigned long long)__float_as_uint(v) << 32)
                        | (unsigned int)(~(unsigned)ci[i]);
        }
    }
    __syncthreads();
    int M = min(sM, SORTN);
    int S = 512;
    while (S < M) S <<= 1;
    for (int i = M + tid; i < S; i += 1024) keys[i] = 0ULL;
    __syncthreads();
    for (int k = 2; k <= S; k <<= 1){
        for (int j = k >> 1; j > 0; j >>= 1){
            for (int i = tid; i < S; i += 1024){
                int ixj = i ^ j;
                if (ixj > i){
                    unsigned long long a = keys[i], c = keys[ixj];
                    bool up = ((i & k) == 0);
                    if ((a > c) == up){ keys[i] = c; keys[ixj] = a; }
                }
            }
            __syncthreads();
        }
    }
    if (tid < KP){
        s_ti[tid] = (int)(~(unsigned)(keys[S-1-tid] & 0xffffffffu));
        avail[tid] = 1;
    }
    __syncthreads();

    int Kv = min(N, KP);
    if (tid == 0){ sCnt = 0; sCur = 0; }
    __syncthreads();
    for (int round = 0; round < NPTS; round++){
        if (tid == 0){
            int i = sCur;
            while (i < Kv && !avail[i]) i++;
            if (i < Kv){
                chosenIdx[sCnt] = s_ti[i];
                sCnt++;
                sPick = i;
                sCur = i + 1;
            } else sPick = -1;
        }
        __syncthreads();
        int i = sPick;
        if (i < 0) break;
        int idx = s_ti[i];
        int xi = idx & (HS-1), yi = idx >> 9;
        if (tid < KP && tid > i && tid < Kv && avail[tid]){
            int dx = (s_ti[tid] & (HS-1)) - xi;
            int dy = (s_ti[tid] >> 9) - yi;
            if (dx*dx + dy*dy < 625) avail[tid] = 0;
        }
        __syncthreads();
    }
    int cnt = sCnt;

    if (cnt < NPTS){
        const float* s = g_sal + (size_t)b*NPIX;
        float lv[NPTS]; int li[NPTS];
        #pragma unroll
        for (int k=0;k<NPTS;k++){ lv[k] = -1e30f; li[k] = 0x7fffffff; }
        for (int p = tid; p < NPIX; p += 1024){
            float v = s[p];
            if (v <= lv[NPTS-1]) continue;
            int y = p >> 9, x = p & (HS-1);
            float mp = v;
            #pragma unroll
            for (int dy=-1; dy<=1; dy++){
                int yy = y + dy; if (yy < 0 || yy >= HS) continue;
                #pragma unroll
                for (int dx=-1; dx<=1; dx++){
                    int xx = x + dx; if (xx < 0 || xx >= HS) continue;
                    mp = fmaxf(mp, s[yy*HS + xx]);
                }
            }
            if (v == mp) continue;
            float cvv = v; int cix = p;
            #pragma unroll
            for (int k=0;k<NPTS;k++){
                bool better = (cvv > lv[k]) || (cvv == lv[k] && cix < li[k]);
                float tv = lv[k]; int ti = li[k];
                if (better){ lv[k] = cvv; li[k] = cix; cvv = tv; cix = ti; }
            }
        }
        int ptr = 0;
        for (int r = 0; r < NPTS; r++){
            unsigned long long mykey = 0ULL;
            if (ptr < NPTS && lv[ptr] > -1e29f)
                mykey = ((unsigned long long)__float_as_uint(lv[ptr]) << 32)
                      | (unsigned int)(~(unsigned)li[ptr]);
            bestkey[tid] = mykey;
            __syncthreads();
            for (int st = 512; st > 0; st >>= 1){
                if (tid < st){
                    unsigned long long o = bestkey[tid+st];
                    if (o > bestkey[tid]) bestkey[tid] = o;
                }
                __syncthreads();
            }
            unsigned long long win = bestkey[0];
            if (tid == 0){ fbIdx[r] = (int)(~(unsigned)(win & 0xffffffffu)); sWin = win; }
            __syncthreads();
            if (mykey != 0ULL && mykey == sWin) ptr++;
            __syncthreads();
        }
    }

    if (tid < NPTS){
        int si = (tid < cnt) ? chosenIdx[tid] : fbIdx[tid - cnt];
        out[b*20 + tid*2 + 0] = (float)(si & (HS-1)) * (1.0f/512.0f);
        out[b*20 + tid*2 + 1] = (float)(si >> 9)     * (1.0f/512.0f);
        out[BATCH*NPTS*2 + b*NPTS + tid] = 1.0f;
    }
}

// ---------------- launch ----------------
extern "C" void kernel_launch(void* const* d_in, const int* in_sizes, int n_in,
                              void* d_out, int out_size){
    (void)in_sizes; (void)n_in; (void)out_size;
    const float* rgb = (const float*)d_in[0];
    const float* dep = (const float*)d_in[1];
    const float* w1  = (const float*)d_in[2];
    const float* b1  = (const float*)d_in[3];
    const float* gam = (const float*)d_in[4];
    const float* bet = (const float*)d_in[5];
    const float* mu  = (const float*)d_in[6];
    const float* var = (const float*)d_in[7];
    const float* w2  = (const float*)d_in[8];
    const float* b2  = (const float*)d_in[9];
    float* out = (float*)d_out;
    float* masks = out + (BATCH*NPTS*2 + BATCH*NPTS + BATCH*4);  // 272

    dim3 blk(32,8);
    kw_reorder<<<32, 256>>>(w1);
    void* wsrc = nullptr;
    cudaGetSymbolAddress(&wsrc, g_wre);
    cudaMemcpyToSymbolAsync(cW, wsrc, 3456*sizeof(float), 0, cudaMemcpyDeviceToDevice, 0);

    k3_conv<<<dim3(16,32,BATCH), 256>>>(rgb,dep,b1,gam,bet,mu,var,w2,b2);
    k45_mask_peaks<<<dim3(16,32,BATCH), blk>>>(masks);
    cudaFuncSetAttribute(k6_points, cudaFuncAttributeMaxDynamicSharedMemorySize, 86528);
    k6_points<<<2*BATCH, 1024, 86528>>>(out);
}